// round 10
// baseline (speedup 1.0000x reference)
#include <cuda_runtime.h>

#define NN    50000
#define DD    128
#define EE    600000
#define NPRED 200000
#define NSEL  300000
#define UD    256
#define NB    49          // scan blocks: 49*1024 >= NN
#define NSM   148
#define NT64  ((NN + 63) / 64)   // 782 row-tiles

typedef unsigned long long ull;

// packed f32x2 helpers (sm_103a FFMA2 — only reachable via PTX)
#define FMA2(d, a, b) asm("fma.rn.f32x2 %0, %1, %2, %0;" : "+l"(d) : "l"(a), "l"(b))
#define UNPACK2(lo, hi, s) asm("mov.b64 {%0, %1}, %2;" : "=f"(lo), "=f"(hi) : "l"(s))

// ---------------- scratch (device globals: allocation-free) ----------------
__device__ int   g_deg_in[NN];
__device__ int   g_deg_out[NN];
__device__ float g_rin[NN];
__device__ float g_rout[NN];
__device__ int   g_off[NN + 1];
__device__ int   g_cur[NN];
__device__ int   g_srcs[EE];
__device__ int   g_bsum[NB];
__device__ float g_bufA[(size_t)NN * DD];   // gemm1 out: (X*rout)@W1
__device__ float g_bufB[(size_t)NN * DD];   // ag2 out:   (h1*rout)@W2
__device__ float g_prob[(size_t)NN * 2];

// ---------------- degree counting ----------------
__global__ void k_zero() {
    int i = blockIdx.x * blockDim.x + threadIdx.x;
    if (i < NN) { g_deg_in[i] = 0; g_deg_out[i] = 0; }
}

__global__ void k_count(const int* __restrict__ ei) {
    int e = blockIdx.x * blockDim.x + threadIdx.x;
    if (e < EE) {
        atomicAdd(&g_deg_out[ei[e]], 1);
        atomicAdd(&g_deg_in[ei[EE + e]], 1);
    }
}

// ---------------- scan pass A (+ fused rsqrt) ----------------
__global__ void k_scan_a() {
    __shared__ int wsum[32];
    int tid  = threadIdx.x;
    int i    = blockIdx.x * 1024 + tid;
    int lane = tid & 31, wid = tid >> 5;
    int v = (i < NN) ? g_deg_in[i] : 0;

    if (i < NN) {
        int dout = g_deg_out[i]; if (dout < 1) dout = 1;
        int din  = v;            if (din  < 1) din  = 1;
        g_rout[i] = rsqrtf((float)dout);
        g_rin[i]  = rsqrtf((float)din);
    }

    int x = v;
    #pragma unroll
    for (int s = 1; s < 32; s <<= 1) {
        int t = __shfl_up_sync(0xffffffffu, x, s);
        if (lane >= s) x += t;
    }
    if (lane == 31) wsum[wid] = x;
    __syncthreads();
    if (wid == 0) {
        int y = wsum[lane];
        #pragma unroll
        for (int s = 1; s < 32; s <<= 1) {
            int t = __shfl_up_sync(0xffffffffu, y, s);
            if (lane >= s) y += t;
        }
        wsum[lane] = y;
    }
    __syncthreads();

    int excl = x - v + (wid ? wsum[wid - 1] : 0);
    if (i < NN) g_off[i] = excl;
    if (tid == 1023) g_bsum[blockIdx.x] = excl + v;
}

// ---------------- scan pass C ----------------
__global__ void k_scan_c() {
    __shared__ int s_pre;
    int tid = threadIdx.x;
    if (tid == 0) {
        int run = 0;
        #pragma unroll
        for (int b = 0; b < NB; b++) {
            if (b == blockIdx.x) s_pre = run;
            run += g_bsum[b];
        }
        if (blockIdx.x == 0) g_off[NN] = run;
    }
    __syncthreads();
    int i = blockIdx.x * 1024 + tid;
    if (i < NN) {
        int o = g_off[i] + s_pre;
        g_off[i] = o;
        g_cur[i] = o;
    }
}

// ---------------- CSR fill ----------------
__global__ void k_fill(const int* __restrict__ ei) {
    int e = blockIdx.x * blockDim.x + threadIdx.x;
    if (e < EE) {
        int d = ei[EE + e];
        int slot = atomicAdd(&g_cur[d], 1);
        g_srcs[slot] = ei[e];
    }
}

// ---------------- warp-private CSR aggregation of one 128-float row ----------
// returns lane's float4 slice of sum_{src in in(gi)} src_rows; unroll-4 for MLP
__device__ __forceinline__ float4 agg_row(const float* __restrict__ src_buf,
                                          int gi, int lane) {
    int lo = g_off[gi], hi = g_off[gi + 1];
    float4 s0 = make_float4(0.f, 0.f, 0.f, 0.f), s1 = s0, s2 = s0, s3 = s0;
    int j = lo;
    for (; j + 4 <= hi; j += 4) {
        int i0 = g_srcs[j], i1 = g_srcs[j + 1], i2 = g_srcs[j + 2], i3 = g_srcs[j + 3];
        float4 v0 = *(const float4*)(src_buf + (size_t)i0 * DD + lane * 4);
        float4 v1 = *(const float4*)(src_buf + (size_t)i1 * DD + lane * 4);
        float4 v2 = *(const float4*)(src_buf + (size_t)i2 * DD + lane * 4);
        float4 v3 = *(const float4*)(src_buf + (size_t)i3 * DD + lane * 4);
        s0.x += v0.x; s0.y += v0.y; s0.z += v0.z; s0.w += v0.w;
        s1.x += v1.x; s1.y += v1.y; s1.z += v1.z; s1.w += v1.w;
        s2.x += v2.x; s2.y += v2.y; s2.z += v2.z; s2.w += v2.w;
        s3.x += v3.x; s3.y += v3.y; s3.z += v3.z; s3.w += v3.w;
    }
    for (; j < hi; j++) {
        int i0 = g_srcs[j];
        float4 v0 = *(const float4*)(src_buf + (size_t)i0 * DD + lane * 4);
        s0.x += v0.x; s0.y += v0.y; s0.z += v0.z; s0.w += v0.w;
    }
    s0.x += s1.x + s2.x + s3.x;
    s0.y += s1.y + s2.y + s3.y;
    s0.z += s1.z + s2.z + s3.z;
    s0.w += s1.w + s2.w + s3.w;
    return s0;
}

// ---------------- 128-col FMA2 GEMM mainloop over this warp's 8 Xs rows ------
// writes result rows to dst[gi*DD + 4*lane .. +3]
__device__ __forceinline__ void gemm_rows128(const float* __restrict__ Xs,
                                             const ull* __restrict__ Wp,
                                             float* __restrict__ dst,
                                             int m0, int wid, int lane) {
    ull acc[8][4];
    #pragma unroll
    for (int r = 0; r < 8; r++)
        #pragma unroll
        for (int c = 0; c < 4; c++) acc[r][c] = 0ull;

    #pragma unroll 8
    for (int kp = 0; kp < DD / 2; kp++) {
        ulonglong2 bb0 = *(const ulonglong2*)(Wp + kp * DD + 4 * lane);
        ulonglong2 bb1 = *(const ulonglong2*)(Wp + kp * DD + 4 * lane + 2);
        ull a2[8];
        #pragma unroll
        for (int r = 0; r < 8; r++)
            a2[r] = *(const ull*)(Xs + (wid * 8 + r) * DD + 2 * kp);   // broadcast
        #pragma unroll
        for (int r = 0; r < 8; r++) {
            FMA2(acc[r][0], a2[r], bb0.x);
            FMA2(acc[r][1], a2[r], bb0.y);
            FMA2(acc[r][2], a2[r], bb1.x);
            FMA2(acc[r][3], a2[r], bb1.y);
        }
    }

    #pragma unroll
    for (int r = 0; r < 8; r++) {
        int gi = m0 + wid * 8 + r;
        if (gi < NN) {
            float4 o;
            float lo, hi;
            UNPACK2(lo, hi, acc[r][0]); o.x = lo + hi;
            UNPACK2(lo, hi, acc[r][1]); o.y = lo + hi;
            UNPACK2(lo, hi, acc[r][2]); o.z = lo + hi;
            UNPACK2(lo, hi, acc[r][3]); o.w = lo + hi;
            *(float4*)(dst + (size_t)gi * DD + 4 * lane) = o;
        }
    }
}

// ---------------- layer-1 GEMM: bufA = (node_state*rout)@W1 (persistent) -----
__global__ void __launch_bounds__(256, 2)
k_gemm1(const float* __restrict__ X, const float* __restrict__ W) {
    extern __shared__ float sm[];
    float* Ws2 = sm;              // 64 kp x 128 cols x float2 (64 KB)
    float* Xs  = sm + DD * DD;    // 64 x 128

    int tid = threadIdx.x, wid = tid >> 5, lane = tid & 31;

    {   // stage W1 k-pair interleaved, once
        float2* Wd = (float2*)Ws2;
        #pragma unroll
        for (int q = 0; q < 32; q++) {
            int idx = tid + 256 * q;
            int kp = idx >> 7, c = idx & 127;
            Wd[idx] = make_float2(W[(2 * kp) * DD + c], W[(2 * kp + 1) * DD + c]);
        }
    }
    __syncthreads();
    const ull* Wp = (const ull*)Ws2;

    for (int tile = blockIdx.x; tile < NT64; tile += 2 * NSM) {
        int m0 = tile * 64;
        // warp-private: load+scale own 8 rows
        #pragma unroll
        for (int q = 0; q < 8; q++) {
            int gi = m0 + wid * 8 + q;
            float4 v = make_float4(0.f, 0.f, 0.f, 0.f);
            if (gi < NN) {
                v = *(const float4*)(X + (size_t)gi * DD + 4 * lane);
                float sc = g_rout[gi];
                v.x *= sc; v.y *= sc; v.z *= sc; v.w *= sc;
            }
            *(float4*)(Xs + (wid * 8 + q) * DD + 4 * lane) = v;
        }
        __syncwarp();
        gemm_rows128(Xs, Wp, g_bufA, m0, wid, lane);
        __syncwarp();
    }
}

// ---------------- fused agg1 + layer-2 GEMM (persistent) ---------------------
// h1 = agg(bufA)*rin + b1 ; bufB = (h1*rout)@W2
__global__ void __launch_bounds__(256, 2)
k_ag2(const float* __restrict__ b1, const float* __restrict__ W) {
    extern __shared__ float sm[];
    float* Ws2 = sm;
    float* Xs  = sm + DD * DD;

    int tid = threadIdx.x, wid = tid >> 5, lane = tid & 31;

    {
        float2* Wd = (float2*)Ws2;
        #pragma unroll
        for (int q = 0; q < 32; q++) {
            int idx = tid + 256 * q;
            int kp = idx >> 7, c = idx & 127;
            Wd[idx] = make_float2(W[(2 * kp) * DD + c], W[(2 * kp + 1) * DD + c]);
        }
    }
    __syncthreads();
    const ull* Wp = (const ull*)Ws2;
    float4 bv = *(const float4*)(b1 + 4 * lane);

    for (int tile = blockIdx.x; tile < NT64; tile += 2 * NSM) {
        int m0 = tile * 64;
        #pragma unroll
        for (int q = 0; q < 8; q++) {
            int gi = m0 + wid * 8 + q;
            float4 v = make_float4(0.f, 0.f, 0.f, 0.f);
            if (gi < NN) {
                float4 s = agg_row(g_bufA, gi, lane);
                float ri = g_rin[gi], ro = g_rout[gi];
                v.x = (s.x * ri + bv.x) * ro;
                v.y = (s.y * ri + bv.y) * ro;
                v.z = (s.z * ri + bv.z) * ro;
                v.w = (s.w * ri + bv.w) * ro;
            }
            *(float4*)(Xs + (wid * 8 + q) * DD + 4 * lane) = v;
        }
        __syncwarp();
        gemm_rows128(Xs, Wp, g_bufB, m0, wid, lane);
        __syncwarp();
    }
}

// ---------------- fused agg2 + dense(128->256)+relu+out+softmax (persistent) -
// h2 = agg(bufB)*rin + b2 ; P[node] = softmax(relu(h2@dW+db)@oW+ob)
__global__ void __launch_bounds__(256, 1)
k_dense(const float* __restrict__ b2,
        const float* __restrict__ dW,
        const float* __restrict__ db,
        const float* __restrict__ oW,
        const float* __restrict__ ob) {
    extern __shared__ float sm[];
    float* Ws2  = sm;                  // 64 kp x 256 cols x float2 (128 KB)
    float* Xs   = Ws2 + DD * UD;       // 64 x 128
    float* s_db = Xs + 64 * DD;        // 256
    float* s_oW = s_db + UD;           // 512
    __shared__ float s_ob[2];

    int tid = threadIdx.x, wid = tid >> 5, lane = tid & 31;

    {
        float2* Wd = (float2*)Ws2;
        #pragma unroll
        for (int q = 0; q < 64; q++) {
            int idx = tid + 256 * q;
            int kp = idx >> 8, c = idx & 255;
            Wd[idx] = make_float2(dW[(2 * kp) * UD + c], dW[(2 * kp + 1) * UD + c]);
        }
    }
    if (tid < UD) {
        s_db[tid]         = db[tid];
        s_oW[tid * 2]     = oW[tid * 2];
        s_oW[tid * 2 + 1] = oW[tid * 2 + 1];
    }
    if (tid < 2) s_ob[tid] = ob[tid];
    __syncthreads();

    const ull* Wp = (const ull*)Ws2;
    float4 bv = *(const float4*)(b2 + 4 * lane);

    for (int tile = blockIdx.x; tile < NT64; tile += NSM) {
        int m0 = tile * 64;

        // warp-private: aggregate own 8 rows of h2
        #pragma unroll
        for (int q = 0; q < 8; q++) {
            int gi = m0 + wid * 8 + q;
            float4 v = make_float4(0.f, 0.f, 0.f, 0.f);
            if (gi < NN) {
                float4 s = agg_row(g_bufB, gi, lane);
                float ri = g_rin[gi];
                v.x = s.x * ri + bv.x;
                v.y = s.y * ri + bv.y;
                v.z = s.z * ri + bv.z;
                v.w = s.w * ri + bv.w;
            }
            *(float4*)(Xs + (wid * 8 + q) * DD + 4 * lane) = v;
        }
        __syncwarp();

        ull acc[8][8];
        #pragma unroll
        for (int r = 0; r < 8; r++)
            #pragma unroll
            for (int c = 0; c < 8; c++) acc[r][c] = 0ull;

        #pragma unroll 4
        for (int kp = 0; kp < DD / 2; kp++) {
            ull b2r[8];
            #pragma unroll
            for (int c = 0; c < 8; c++)
                b2r[c] = Wp[kp * UD + 32 * c + lane];       // conflict-free LDS.64
            ull a2[8];
            #pragma unroll
            for (int r = 0; r < 8; r++)
                a2[r] = *(const ull*)(Xs + (wid * 8 + r) * DD + 2 * kp);  // broadcast
            #pragma unroll
            for (int r = 0; r < 8; r++)
                #pragma unroll
                for (int c = 0; c < 8; c++)
                    FMA2(acc[r][c], a2[r], b2r[c]);
        }

        // epilogue: relu + 256->2, warp reduce, softmax -> g_prob[node]
        #pragma unroll
        for (int r = 0; r < 8; r++) {
            float p0 = 0.f, p1 = 0.f;
            #pragma unroll
            for (int c = 0; c < 8; c++) {
                float lo, hi;
                UNPACK2(lo, hi, acc[r][c]);
                int col = 32 * c + lane;
                float v = fmaxf(lo + hi + s_db[col], 0.f);
                p0 = fmaf(v, s_oW[col * 2],     p0);
                p1 = fmaf(v, s_oW[col * 2 + 1], p1);
            }
            #pragma unroll
            for (int o = 16; o; o >>= 1) {
                p0 += __shfl_down_sync(0xffffffffu, p0, o);
                p1 += __shfl_down_sync(0xffffffffu, p1, o);
            }
            if (lane == 0) {
                int gi = m0 + wid * 8 + r;
                if (gi < NN) {
                    float z0 = p0 + s_ob[0], z1 = p1 + s_ob[1];
                    float m  = fmaxf(z0, z1);
                    float e0 = __expf(z0 - m), e1 = __expf(z1 - m);
                    float inv = 1.f / (e0 + e1);
                    *(float2*)(g_prob + (size_t)gi * 2) = make_float2(e0 * inv, e1 * inv);
                }
            }
        }
        __syncwarp();
    }
}

// ---------------- output gather: out[i] = P[oe[set_idx[i]]] ----------------
__global__ void k_out(const int* __restrict__ set_idx,
                      const int* __restrict__ oe,
                      float* __restrict__ out) {
    int i = blockIdx.x * blockDim.x + threadIdx.x;
    if (i < NSEL) {
        int node = oe[set_idx[i]];
        *(float2*)(out + (size_t)i * 2) = *(const float2*)(g_prob + (size_t)node * 2);
    }
}

// ---------------- host launch ----------------
extern "C" void kernel_launch(void* const* d_in, const int* in_sizes, int n_in,
                              void* d_out, int out_size) {
    const float* node_state = (const float*)d_in[0];
    const int*   edge_index = (const int*)d_in[1];
    const int*   out_edges  = (const int*)d_in[2];
    const int*   set_idx    = (const int*)d_in[3];
    const float* W1         = (const float*)d_in[4];
    const float* b1         = (const float*)d_in[5];
    const float* W2         = (const float*)d_in[6];
    const float* b2         = (const float*)d_in[7];
    const float* dW         = (const float*)d_in[8];
    const float* db         = (const float*)d_in[9];
    const float* oW         = (const float*)d_in[10];
    const float* ob         = (const float*)d_in[11];
    float* out = (float*)d_out;

    const int GEMM_SMEM  = (DD * DD + 64 * DD) * 4;                  // 96 KB
    const int DENSE_SMEM = (DD * UD + 64 * DD + UD + 2 * UD) * 4;    // ~163 KB

    cudaFuncSetAttribute(k_gemm1, cudaFuncAttributeMaxDynamicSharedMemorySize, GEMM_SMEM);
    cudaFuncSetAttribute(k_ag2,   cudaFuncAttributeMaxDynamicSharedMemorySize, GEMM_SMEM);
    cudaFuncSetAttribute(k_dense, cudaFuncAttributeMaxDynamicSharedMemorySize, DENSE_SMEM);

    k_zero   <<<(NN + 255) / 256, 256>>>();
    k_count  <<<(EE + 255) / 256, 256>>>(edge_index);
    k_scan_a <<<NB, 1024>>>();
    k_scan_c <<<NB, 1024>>>();
    k_fill   <<<(EE + 255) / 256, 256>>>(edge_index);

    k_gemm1<<<2 * NSM, 256, GEMM_SMEM>>>(node_state, W1);   // launch #6 <- profiled
    k_ag2  <<<2 * NSM, 256, GEMM_SMEM>>>(b1, W2);
    k_dense<<<NSM, 256, DENSE_SMEM>>>(b2, dW, db, oW, ob);
    k_out  <<<(NSEL + 255) / 256, 256>>>(set_idx, out_edges, out);
}

// round 11
// speedup vs baseline: 1.1881x; 1.1881x over previous
#include <cuda_runtime.h>

#define NN    50000
#define DD    128
#define EE    600000
#define NPRED 200000
#define NSEL  300000
#define UD    256
#define NB    49          // scan blocks: 49*1024 >= NN
#define NSM   148
#define NT64  ((NN + 63) / 64)   // 782 row-tiles

typedef unsigned long long ull;

// packed f32x2 helpers (sm_103a FFMA2 — only reachable via PTX)
#define FMA2(d, a, b) asm("fma.rn.f32x2 %0, %1, %2, %0;" : "+l"(d) : "l"(a), "l"(b))
#define UNPACK2(lo, hi, s) asm("mov.b64 {%0, %1}, %2;" : "=f"(lo), "=f"(hi) : "l"(s))

// ---------------- scratch (device globals: allocation-free) ----------------
__device__ int   g_deg_in[NN];
__device__ int   g_deg_out[NN];
__device__ float g_rin[NN];
__device__ float g_rout[NN];
__device__ int   g_off[NN + 1];
__device__ int   g_cur[NN];
__device__ int   g_srcs[EE];
__device__ int   g_bsum[NB];
__device__ float g_bufA[(size_t)NN * DD];
__device__ float g_bufB[(size_t)NN * DD];
__device__ float g_part[(size_t)NN * 4];   // [node][half*2 + {p0,p1}]

// ---------------- degree counting ----------------
__global__ void k_zero() {
    int i = blockIdx.x * blockDim.x + threadIdx.x;
    if (i < NN) { g_deg_in[i] = 0; g_deg_out[i] = 0; }
}

__global__ void k_count(const int* __restrict__ ei) {
    int e = blockIdx.x * blockDim.x + threadIdx.x;
    if (e < EE) {
        atomicAdd(&g_deg_out[ei[e]], 1);
        atomicAdd(&g_deg_in[ei[EE + e]], 1);
    }
}

// ---------------- scan pass A (+ fused rsqrt) ----------------
__global__ void k_scan_a() {
    __shared__ int wsum[32];
    int tid  = threadIdx.x;
    int i    = blockIdx.x * 1024 + tid;
    int lane = tid & 31, wid = tid >> 5;
    int v = (i < NN) ? g_deg_in[i] : 0;

    if (i < NN) {
        int dout = g_deg_out[i]; if (dout < 1) dout = 1;
        int din  = v;            if (din  < 1) din  = 1;
        g_rout[i] = rsqrtf((float)dout);
        g_rin[i]  = rsqrtf((float)din);
    }

    int x = v;
    #pragma unroll
    for (int s = 1; s < 32; s <<= 1) {
        int t = __shfl_up_sync(0xffffffffu, x, s);
        if (lane >= s) x += t;
    }
    if (lane == 31) wsum[wid] = x;
    __syncthreads();
    if (wid == 0) {
        int y = wsum[lane];
        #pragma unroll
        for (int s = 1; s < 32; s <<= 1) {
            int t = __shfl_up_sync(0xffffffffu, y, s);
            if (lane >= s) y += t;
        }
        wsum[lane] = y;
    }
    __syncthreads();

    int excl = x - v + (wid ? wsum[wid - 1] : 0);
    if (i < NN) g_off[i] = excl;
    if (tid == 1023) g_bsum[blockIdx.x] = excl + v;
}

// ---------------- scan pass C ----------------
__global__ void k_scan_c() {
    __shared__ int s_pre;
    int tid = threadIdx.x;
    if (tid == 0) {
        int run = 0;
        #pragma unroll
        for (int b = 0; b < NB; b++) {
            if (b == blockIdx.x) s_pre = run;
            run += g_bsum[b];
        }
        if (blockIdx.x == 0) g_off[NN] = run;
    }
    __syncthreads();
    int i = blockIdx.x * 1024 + tid;
    if (i < NN) {
        int o = g_off[i] + s_pre;
        g_off[i] = o;
        g_cur[i] = o;
    }
}

// ---------------- CSR fill ----------------
__global__ void k_fill(const int* __restrict__ ei) {
    int e = blockIdx.x * blockDim.x + threadIdx.x;
    if (e < EE) {
        int d = ei[EE + e];
        int slot = atomicAdd(&g_cur[d], 1);
        g_srcs[slot] = ei[e];
    }
}

// ---------------- conv GEMM (persistent, k-pair f32x2): dst = (X*rout)@W -----
// grid 2*NSM x 256 thr, 2 CTA/SM. Warp-private X rows -> __syncwarp only.
__global__ void __launch_bounds__(256, 2)
k_gemm(const float* __restrict__ Xext, const float* __restrict__ W,
       float* __restrict__ dst, int useB) {
    extern __shared__ float sm[];
    float* Ws2 = sm;              // 64 kp x 128 cols x float2 (64 KB)
    float* Xs  = sm + DD * DD;    // 64 x 128
    const float* X = useB ? (const float*)g_bufB : Xext;

    int tid = threadIdx.x, wid = tid >> 5, lane = tid & 31;

    {   // stage W k-pair interleaved, once
        float2* Wd = (float2*)Ws2;
        #pragma unroll
        for (int q = 0; q < 32; q++) {
            int idx = tid + 256 * q;
            int kp = idx >> 7, c = idx & 127;
            Wd[idx] = make_float2(W[(2 * kp) * DD + c], W[(2 * kp + 1) * DD + c]);
        }
    }
    __syncthreads();
    const ull* Wp = (const ull*)Ws2;

    for (int tile = blockIdx.x; tile < NT64; tile += 2 * NSM) {
        int m0 = tile * 64;
        #pragma unroll
        for (int q = 0; q < 8; q++) {
            int gi = m0 + wid * 8 + q;
            float4 v = make_float4(0.f, 0.f, 0.f, 0.f);
            if (gi < NN) {
                v = *(const float4*)(X + (size_t)gi * DD + 4 * lane);
                float sc = g_rout[gi];
                v.x *= sc; v.y *= sc; v.z *= sc; v.w *= sc;
            }
            *(float4*)(Xs + (wid * 8 + q) * DD + 4 * lane) = v;
        }
        __syncwarp();

        ull acc[8][4];
        #pragma unroll
        for (int r = 0; r < 8; r++)
            #pragma unroll
            for (int c = 0; c < 4; c++) acc[r][c] = 0ull;

        #pragma unroll 8
        for (int kp = 0; kp < DD / 2; kp++) {
            ulonglong2 bb0 = *(const ulonglong2*)(Wp + kp * DD + 4 * lane);
            ulonglong2 bb1 = *(const ulonglong2*)(Wp + kp * DD + 4 * lane + 2);
            ull a2[8];
            #pragma unroll
            for (int r = 0; r < 8; r++)
                a2[r] = *(const ull*)(Xs + (wid * 8 + r) * DD + 2 * kp);  // broadcast
            #pragma unroll
            for (int r = 0; r < 8; r++) {
                FMA2(acc[r][0], a2[r], bb0.x);
                FMA2(acc[r][1], a2[r], bb0.y);
                FMA2(acc[r][2], a2[r], bb1.x);
                FMA2(acc[r][3], a2[r], bb1.y);
            }
        }

        #pragma unroll
        for (int r = 0; r < 8; r++) {
            int gi = m0 + wid * 8 + r;
            if (gi < NN) {
                float4 o;
                float lo, hi;
                UNPACK2(lo, hi, acc[r][0]); o.x = lo + hi;
                UNPACK2(lo, hi, acc[r][1]); o.y = lo + hi;
                UNPACK2(lo, hi, acc[r][2]); o.z = lo + hi;
                UNPACK2(lo, hi, acc[r][3]); o.w = lo + hi;
                *(float4*)(dst + (size_t)gi * DD + 4 * lane) = o;
            }
        }
        __syncwarp();
    }
}

// ---------------- aggregation (separate, high-occupancy): bufB = rin*agg(bufA)+b
__global__ void k_agg(const float* __restrict__ bias) {
    int t = blockIdx.x * blockDim.x + threadIdx.x;
    int w = t >> 5, lane = t & 31;
    if (w >= NN) return;
    int lo = g_off[w], hi = g_off[w + 1];
    float4 acc = make_float4(0.f, 0.f, 0.f, 0.f);
    for (int j = lo; j < hi; j++) {
        int s = g_srcs[j];
        float4 v = *(const float4*)(g_bufA + (size_t)s * DD + lane * 4);
        acc.x += v.x; acc.y += v.y; acc.z += v.z; acc.w += v.w;
    }
    float r = g_rin[w];
    float4 bb = *(const float4*)(bias + lane * 4);
    float4 o;
    o.x = acc.x * r + bb.x; o.y = acc.y * r + bb.y;
    o.z = acc.z * r + bb.z; o.w = acc.w * r + bb.w;
    *(float4*)(g_bufB + (size_t)w * DD + lane * 4) = o;
}

// ---------------- dense head, HALF-SPLIT: 2 CTA/SM, each CTA owns 128 cols ---
// h2 rows in bufB. partial (p0,p1) over this half's cols -> g_part[node][half].
// grid 2*NSM: half = bid&1, tileStart = bid>>1, stride NSM over 782 tiles.
__global__ void __launch_bounds__(256, 2)
k_dense(const float* __restrict__ dW,
        const float* __restrict__ db,
        const float* __restrict__ oW) {
    extern __shared__ float sm[];
    float* Ws2  = sm;                  // 64 kp x 128 cols x float2 (64 KB)
    float* Xs   = Ws2 + DD * DD;       // 64 x 128 (32 KB)
    float* s_db = Xs + 64 * DD;        // 128
    float* s_oW = s_db + 128;          // 256

    int tid  = threadIdx.x, wid = tid >> 5, lane = tid & 31;
    int half = blockIdx.x & 1;
    int cbase = half * 128;

    {   // stage this half of dense_W, k-pair interleaved
        float2* Wd = (float2*)Ws2;
        #pragma unroll
        for (int q = 0; q < 32; q++) {
            int idx = tid + 256 * q;          // 0..8191
            int kp = idx >> 7, c = idx & 127;
            Wd[idx] = make_float2(dW[(2 * kp) * UD + cbase + c],
                                  dW[(2 * kp + 1) * UD + cbase + c]);
        }
    }
    if (tid < 128) {
        s_db[tid]         = db[cbase + tid];
        s_oW[tid * 2]     = oW[(cbase + tid) * 2];
        s_oW[tid * 2 + 1] = oW[(cbase + tid) * 2 + 1];
    }
    __syncthreads();
    const ull* Wp = (const ull*)Ws2;

    for (int tile = blockIdx.x >> 1; tile < NT64; tile += NSM) {
        int m0 = tile * 64;
        #pragma unroll
        for (int q = 0; q < 8; q++) {
            int gi = m0 + wid * 8 + q;
            float4 v = make_float4(0.f, 0.f, 0.f, 0.f);
            if (gi < NN)
                v = *(const float4*)(g_bufB + (size_t)gi * DD + 4 * lane);
            *(float4*)(Xs + (wid * 8 + q) * DD + 4 * lane) = v;
        }
        __syncwarp();

        ull acc[8][4];
        #pragma unroll
        for (int r = 0; r < 8; r++)
            #pragma unroll
            for (int c = 0; c < 4; c++) acc[r][c] = 0ull;

        #pragma unroll 8
        for (int kp = 0; kp < DD / 2; kp++) {
            ulonglong2 bb0 = *(const ulonglong2*)(Wp + kp * DD + 4 * lane);
            ulonglong2 bb1 = *(const ulonglong2*)(Wp + kp * DD + 4 * lane + 2);
            ull a2[8];
            #pragma unroll
            for (int r = 0; r < 8; r++)
                a2[r] = *(const ull*)(Xs + (wid * 8 + r) * DD + 2 * kp);  // broadcast
            #pragma unroll
            for (int r = 0; r < 8; r++) {
                FMA2(acc[r][0], a2[r], bb0.x);
                FMA2(acc[r][1], a2[r], bb0.y);
                FMA2(acc[r][2], a2[r], bb1.x);
                FMA2(acc[r][3], a2[r], bb1.y);
            }
        }

        // epilogue: relu + partial 128->2, warp reduce, write g_part
        #pragma unroll
        for (int r = 0; r < 8; r++) {
            float p0 = 0.f, p1 = 0.f;
            #pragma unroll
            for (int c = 0; c < 4; c++) {
                float lo, hi;
                UNPACK2(lo, hi, acc[r][c]);
                int col = 4 * lane + c;               // col within half
                float v = fmaxf(lo + hi + s_db[col], 0.f);
                p0 = fmaf(v, s_oW[col * 2],     p0);
                p1 = fmaf(v, s_oW[col * 2 + 1], p1);
            }
            #pragma unroll
            for (int o = 16; o; o >>= 1) {
                p0 += __shfl_down_sync(0xffffffffu, p0, o);
                p1 += __shfl_down_sync(0xffffffffu, p1, o);
            }
            if (lane == 0) {
                int gi = m0 + wid * 8 + r;
                if (gi < NN)
                    *(float2*)(g_part + (size_t)gi * 4 + half * 2) = make_float2(p0, p1);
            }
        }
        __syncwarp();
    }
}

// ---------------- output: combine halves + ob + softmax + gather -------------
__global__ void k_out(const int* __restrict__ set_idx,
                      const int* __restrict__ oe,
                      const float* __restrict__ ob,
                      float* __restrict__ out) {
    int i = blockIdx.x * blockDim.x + threadIdx.x;
    if (i < NSEL) {
        int node = oe[set_idx[i]];
        float4 pt = *(const float4*)(g_part + (size_t)node * 4);
        float z0 = pt.x + pt.z + ob[0];
        float z1 = pt.y + pt.w + ob[1];
        float m  = fmaxf(z0, z1);
        float e0 = __expf(z0 - m), e1 = __expf(z1 - m);
        float inv = 1.f / (e0 + e1);
        *(float2*)(out + (size_t)i * 2) = make_float2(e0 * inv, e1 * inv);
    }
}

// ---------------- host launch ----------------
extern "C" void kernel_launch(void* const* d_in, const int* in_sizes, int n_in,
                              void* d_out, int out_size) {
    const float* node_state = (const float*)d_in[0];
    const int*   edge_index = (const int*)d_in[1];
    const int*   out_edges  = (const int*)d_in[2];
    const int*   set_idx    = (const int*)d_in[3];
    const float* W1         = (const float*)d_in[4];
    const float* b1         = (const float*)d_in[5];
    const float* W2         = (const float*)d_in[6];
    const float* b2         = (const float*)d_in[7];
    const float* dW         = (const float*)d_in[8];
    const float* db         = (const float*)d_in[9];
    const float* oW         = (const float*)d_in[10];
    const float* ob         = (const float*)d_in[11];
    float* out = (float*)d_out;

    const int GEMM_SMEM  = (DD * DD + 64 * DD) * 4;                // 96 KB
    const int DENSE_SMEM = (DD * DD + 64 * DD + 128 + 256) * 4;    // ~97.5 KB

    cudaFuncSetAttribute(k_gemm,  cudaFuncAttributeMaxDynamicSharedMemorySize, GEMM_SMEM);
    cudaFuncSetAttribute(k_dense, cudaFuncAttributeMaxDynamicSharedMemorySize, DENSE_SMEM);

    float* bufA = nullptr; float* bufB = nullptr;   // device-global dsts resolved below
    cudaGetSymbolAddress((void**)&bufA, g_bufA);
    cudaGetSymbolAddress((void**)&bufB, g_bufB);

    k_zero   <<<(NN + 255) / 256, 256>>>();
    k_count  <<<(EE + 255) / 256, 256>>>(edge_index);
    k_scan_a <<<NB, 1024>>>();
    k_scan_c <<<NB, 1024>>>();
    k_fill   <<<(EE + 255) / 256, 256>>>(edge_index);

    // layer 1: bufA = (X*rout)@W1 ; bufB = rin*agg(bufA)+b1
    k_gemm<<<2 * NSM, 256, GEMM_SMEM>>>(node_state, W1, bufA, 0);
    k_agg <<<(NN * 32 + 255) / 256, 256>>>(b1);
    // layer 2: bufA = (bufB*rout)@W2 ; bufB = rin*agg(bufA)+b2  (h2)
    k_gemm<<<2 * NSM, 256, GEMM_SMEM>>>(nullptr, W2, bufA, 1);
    k_agg <<<(NN * 32 + 255) / 256, 256>>>(b2);

    // dense head (half-split, 2 CTA/SM) + combine/softmax/gather
    k_dense<<<2 * NSM, 256, DENSE_SMEM>>>(dW, db, oW);
    k_out  <<<(NSEL + 255) / 256, 256>>>(set_idx, out_edges, ob, out);
}